// round 11
// baseline (speedup 1.0000x reference)
#include <cuda_runtime.h>
#include <cstdint>

// Problem constants (fixed by the dataset shapes)
#define DIMS 1024           // embedding dim, fp32
#define VECS_PER_ROW 256    // 1024 floats / 4 per float4
#define MAX_PAIRS 8192
#define VOCAB 50257

#define EPS 1e-8f
#define WEIGHT 0.01f

// Allocation-free scratch
__device__ float g_partial[MAX_PAIRS];    // per-pair (1 - sim)
__device__ unsigned int g_ticket = 0;     // wraps to 0 each launch -> graph-safe

// acq_rel device-scope atomicInc: release orders our prior st.cg, acquire on
// the winning (last) CTA makes everyone else's st.cg visible. No MEMBAR, no
// CCTL.IVALL L1 flush (unlike __threadfence()).
__device__ __forceinline__ unsigned atomic_inc_acqrel(unsigned* addr, unsigned wrap)
{
    unsigned old;
    asm volatile("atom.acq_rel.gpu.global.inc.u32 %0, [%1], %2;"
                 : "=r"(old) : "l"(addr), "r"(wrap) : "memory");
    return old;
}

// One CTA per pair (high warp count = chip-wide latency hiding), fused
// fence-free tail reduction by the last CTA to finish.
__global__ __launch_bounds__(VECS_PER_ROW) void anchor_loss_kernel(
    const float* __restrict__ W,
    const int* __restrict__ archaic_idx,
    const int* __restrict__ modern_idx,
    float* __restrict__ out,
    int n_pairs)
{
    const int p    = blockIdx.x;
    const int t    = threadIdx.x;
    const int warp = t >> 5;
    const int lane = t & 31;

    int ia = __ldg(archaic_idx + p);
    int im = __ldg(modern_idx + p);
    ia = min(max(ia, 0), VOCAB - 1);
    im = min(max(im, 0), VOCAB - 1);

    const float4* __restrict__ a4 =
        reinterpret_cast<const float4*>(W + (size_t)ia * DIMS);
    const float4* __restrict__ m4 =
        reinterpret_cast<const float4*>(W + (size_t)im * DIMS);

    const float4 av = a4[t];
    const float4 mv = m4[t];

    float dot = av.x * mv.x + av.y * mv.y + av.z * mv.z + av.w * mv.w;
    float na  = av.x * av.x + av.y * av.y + av.z * av.z + av.w * av.w;
    float nm  = mv.x * mv.x + mv.y * mv.y + mv.z * mv.z + mv.w * mv.w;

    #pragma unroll
    for (int off = 16; off > 0; off >>= 1) {
        dot += __shfl_down_sync(0xFFFFFFFFu, dot, off);
        na  += __shfl_down_sync(0xFFFFFFFFu, na,  off);
        nm  += __shfl_down_sync(0xFFFFFFFFu, nm,  off);
    }

    __shared__ float s_dot[8], s_na[8], s_nm[8];
    __shared__ bool  s_last;
    if (lane == 0) {
        s_dot[warp] = dot;
        s_na[warp]  = na;
        s_nm[warp]  = nm;
    }
    __syncthreads();

    if (warp == 0) {
        float d = (lane < 8) ? s_dot[lane] : 0.0f;
        float a = (lane < 8) ? s_na[lane]  : 0.0f;
        float m = (lane < 8) ? s_nm[lane]  : 0.0f;
        #pragma unroll
        for (int off = 4; off > 0; off >>= 1) {
            d += __shfl_down_sync(0xFFFFFFFFu, d, off);
            a += __shfl_down_sync(0xFFFFFFFFu, a, off);
            m += __shfl_down_sync(0xFFFFFFFFu, m, off);
        }
        if (lane == 0) {
            const float den = fmaxf(sqrtf(a), EPS) * fmaxf(sqrtf(m), EPS);
            __stcg(&g_partial[p], 1.0f - d / den);             // straight to L2
            const unsigned tk = atomic_inc_acqrel(&g_ticket, (unsigned)n_pairs - 1u);
            s_last = (tk == (unsigned)n_pairs - 1u);
        }
    }
    __syncthreads();

    // Last CTA: deterministic fixed-order reduction of all partials (L2-hot).
    if (s_last) {
        float s = 0.0f;
        for (int i = t; i < n_pairs; i += VECS_PER_ROW)
            s += __ldcg(&g_partial[i]);                        // L2-direct

        #pragma unroll
        for (int off = 16; off > 0; off >>= 1)
            s += __shfl_down_sync(0xFFFFFFFFu, s, off);

        if (lane == 0) s_dot[warp] = s;   // reuse smem
        __syncthreads();

        if (warp == 0) {
            s = (lane < 8) ? s_dot[lane] : 0.0f;
            #pragma unroll
            for (int off = 4; off > 0; off >>= 1)
                s += __shfl_down_sync(0xFFFFFFFFu, s, off);
            if (lane == 0)
                out[0] = WEIGHT * (s / (float)n_pairs);
        }
    }
}

extern "C" void kernel_launch(void* const* d_in, const int* in_sizes, int n_in,
                              void* d_out, int out_size)
{
    const float* W  = (const float*)d_in[0];   // [50257, 1024] fp32
    const int*   ai = (const int*)d_in[1];     // [n_pairs] int32
    const int*   mi = (const int*)d_in[2];     // [n_pairs] int32
    float* out = (float*)d_out;

    int n_pairs = in_sizes[1];
    if (n_pairs > MAX_PAIRS) n_pairs = MAX_PAIRS;
    if (n_pairs < 1) n_pairs = 1;

    anchor_loss_kernel<<<n_pairs, VECS_PER_ROW>>>(W, ai, mi, out, n_pairs);
}

// round 13
// speedup vs baseline: 1.1750x; 1.1750x over previous
#include <cuda_runtime.h>
#include <cstdint>

// Problem constants (fixed by the dataset shapes)
#define DIMS 1024           // embedding dim, fp32
#define VECS_PER_ROW 256    // 1024 floats / 4 per float4
#define MAX_PAIRS 8192
#define VOCAB 50257

#define EPS 1e-8f
#define WEIGHT 0.01f

#define FIX_BITS 34
#define SUM_MASK ((1ULL << 48) - 1ULL)
#define CNT_ONE  (1ULL << 48)

// Single accumulator: bits [0,48) = fixed-point sum of (1-sim), bits [48,64) =
// completion count. One RELAXED u64 atomicAdd per CTA carries both the data and
// the ticket -> no fences, no MEMBAR, no L1 flush, fully deterministic
// (integer adds commute). The winner atomicExch's it back to 0 for graph replay.
__device__ unsigned long long g_acc = 0ULL;

__global__ __launch_bounds__(VECS_PER_ROW) void anchor_loss_kernel(
    const float* __restrict__ W,
    const int* __restrict__ archaic_idx,
    const int* __restrict__ modern_idx,
    float* __restrict__ out,
    int n_pairs)
{
    const int p    = blockIdx.x;
    const int t    = threadIdx.x;
    const int warp = t >> 5;
    const int lane = t & 31;

    int ia = __ldg(archaic_idx + p);
    int im = __ldg(modern_idx + p);
    ia = min(max(ia, 0), VOCAB - 1);
    im = min(max(im, 0), VOCAB - 1);

    const float4* __restrict__ a4 =
        reinterpret_cast<const float4*>(W + (size_t)ia * DIMS);
    const float4* __restrict__ m4 =
        reinterpret_cast<const float4*>(W + (size_t)im * DIMS);

    const float4 av = a4[t];
    const float4 mv = m4[t];

    float dot = av.x * mv.x + av.y * mv.y + av.z * mv.z + av.w * mv.w;
    float na  = av.x * av.x + av.y * av.y + av.z * av.z + av.w * av.w;
    float nm  = mv.x * mv.x + mv.y * mv.y + mv.z * mv.z + mv.w * mv.w;

    #pragma unroll
    for (int off = 16; off > 0; off >>= 1) {
        dot += __shfl_down_sync(0xFFFFFFFFu, dot, off);
        na  += __shfl_down_sync(0xFFFFFFFFu, na,  off);
        nm  += __shfl_down_sync(0xFFFFFFFFu, nm,  off);
    }

    __shared__ float s_dot[8], s_na[8], s_nm[8];
    if (lane == 0) {
        s_dot[warp] = dot;
        s_na[warp]  = na;
        s_nm[warp]  = nm;
    }
    __syncthreads();

    if (warp == 0) {
        float d = (lane < 8) ? s_dot[lane] : 0.0f;
        float a = (lane < 8) ? s_na[lane]  : 0.0f;
        float m = (lane < 8) ? s_nm[lane]  : 0.0f;
        #pragma unroll
        for (int off = 4; off > 0; off >>= 1) {
            d += __shfl_down_sync(0xFFFFFFFFu, d, off);
            a += __shfl_down_sync(0xFFFFFFFFu, a, off);
            m += __shfl_down_sync(0xFFFFFFFFu, m, off);
        }
        if (lane == 0) {
            const float den  = fmaxf(sqrtf(a), EPS) * fmaxf(sqrtf(m), EPS);
            float loss = 1.0f - d / den;
            loss = fmaxf(loss, 0.0f);   // guard llrint against -ulp noise
            const unsigned long long q =
                (unsigned long long)llrintf(loss * (float)(1ULL << FIX_BITS));

            const unsigned long long old = atomicAdd(&g_acc, CNT_ONE | q);

            if ((old >> 48) == (unsigned long long)(n_pairs - 1)) {
                // Last CTA: read complete total and reset for the next replay.
                const unsigned long long tot = atomicExch(&g_acc, 0ULL);
                const double sum =
                    (double)(tot & SUM_MASK) * (1.0 / (double)(1ULL << FIX_BITS));
                out[0] = (float)((double)WEIGHT * sum / (double)n_pairs);
            }
        }
    }
}

extern "C" void kernel_launch(void* const* d_in, const int* in_sizes, int n_in,
                              void* d_out, int out_size)
{
    const float* W  = (const float*)d_in[0];   // [50257, 1024] fp32
    const int*   ai = (const int*)d_in[1];     // [n_pairs] int32
    const int*   mi = (const int*)d_in[2];     // [n_pairs] int32
    float* out = (float*)d_out;

    int n_pairs = in_sizes[1];
    if (n_pairs > MAX_PAIRS) n_pairs = MAX_PAIRS;
    if (n_pairs < 1) n_pairs = 1;

    anchor_loss_kernel<<<n_pairs, VECS_PER_ROW>>>(W, ai, mi, out, n_pairs);
}